// round 2
// baseline (speedup 1.0000x reference)
#include <cuda_runtime.h>
#include <cuda_fp16.h>
#include <cstdint>

// ============================================================================
// QKVHadamard: kappa[b,i,j,d] = sum_e q[b,i,e] * k[b,j,e] * Wv[d,e]
//   q = t @ Wq^T, k = t @ Wk^T   (B=2, N=512, D=512, d_dir=64)
//
// Per (b,i): kappa[j,d] = sum_e k[j,e] * (q_i[e] * Wv[d,e])
//   -> GEMM 512x512x64, tiled 128(j) x 128(d) per CTA.
// Precision: split-fp16 (hi+lo), 3 passes (Ahi*Bhi + Ahi*Blo + Alo*Bhi),
// fp32 accumulate via mma.sync.m16n8k16 -> rel err ~1e-6.
// ============================================================================

// ---------------------------------------------------------------------------
// scratch for q, k: (B*N, 64) fp32
// ---------------------------------------------------------------------------
__device__ float g_q[1024 * 64];
__device__ float g_k[1024 * 64];

// ---------------------------------------------------------------------------
// Kernel 1: q = t@Wq^T, k = t@Wk^T. One block per (b,n) row. fp32 exact.
// ---------------------------------------------------------------------------
__global__ __launch_bounds__(256) void qk_kernel(
    const float* __restrict__ t,
    const float* __restrict__ Wq,
    const float* __restrict__ Wk)
{
    __shared__ float ts[512];
    int bn = blockIdx.x;                   // 0..1023
    const float* trow = t + (size_t)bn * 512;
    int tid = threadIdx.x;
    ts[tid]       = trow[tid];
    ts[tid + 256] = trow[tid + 256];
    __syncthreads();

    int wid = tid >> 5, lid = tid & 31;
    #pragma unroll
    for (int r = 0; r < 8; r++) {
        int e = wid * 8 + r;               // 0..63
        const float* wq = Wq + (size_t)e * 512;
        const float* wk = Wk + (size_t)e * 512;
        float aq = 0.f, ak = 0.f;
        #pragma unroll 4
        for (int kk = lid; kk < 512; kk += 32) {
            float tv = ts[kk];
            aq += tv * wq[kk];
            ak += tv * wk[kk];
        }
        #pragma unroll
        for (int off = 16; off; off >>= 1) {
            aq += __shfl_xor_sync(0xFFFFFFFFu, aq, off);
            ak += __shfl_xor_sync(0xFFFFFFFFu, ak, off);
        }
        if (lid == 0) {
            g_q[bn * 64 + e] = aq;
            g_k[bn * 64 + e] = ak;
        }
    }
}

// ---------------------------------------------------------------------------
// Kernel 2: per CTA: 128(j) x 128(d) tile of kappa for one (b,i).
// ---------------------------------------------------------------------------
// SMEM: 4 half arrays, 128 rows x 64 cols, row pitch 72 halves (144 bytes).
// 144B = 36 banks -> rows shift 4 banks: the (8 rows x 4 lanes) fragment
// access pattern is bank-conflict-free without ldmatrix.
static constexpr int PITCH_H   = 72;                  // halves per row
static constexpr int PITCH_B   = PITCH_H * 2;         // 144 bytes
static constexpr int ARR_BYTES = 128 * PITCH_B;       // 18432
static constexpr int SM_A_HI = 0;
static constexpr int SM_A_LO = ARR_BYTES;
static constexpr int SM_B_HI = 2 * ARR_BYTES;
static constexpr int SM_B_LO = 3 * ARR_BYTES;
static constexpr int SM_QS   = 4 * ARR_BYTES;         // 64 floats
static constexpr int SMEM_TOTAL = SM_QS + 64 * 4;     // 73984 bytes

__device__ __forceinline__ void mma16816(float* c, const uint32_t* a, const uint32_t* b) {
    asm volatile(
        "mma.sync.aligned.m16n8k16.row.col.f32.f16.f16.f32 "
        "{%0,%1,%2,%3}, {%4,%5,%6,%7}, {%8,%9}, {%0,%1,%2,%3};"
        : "+f"(c[0]), "+f"(c[1]), "+f"(c[2]), "+f"(c[3])
        : "r"(a[0]), "r"(a[1]), "r"(a[2]), "r"(a[3]), "r"(b[0]), "r"(b[1]));
}

__global__ __launch_bounds__(256, 2) void kappa_kernel(
    const float* __restrict__ Wv,
    float* __restrict__ out)
{
    extern __shared__ char smem[];

    int tid = threadIdx.x, wid = tid >> 5, lid = tid & 31;

    int idx = blockIdx.x;
    int bi  = idx >> 4;          // 0..1023  (b*512 + i)
    int jt  = (idx >> 2) & 3;    // j tile
    int dt  = idx & 3;           // d tile
    int b   = bi >> 9;
    int j0  = jt * 128;
    int d0  = dt * 128;

    // q_i into smem
    float* qs = (float*)(smem + SM_QS);
    if (tid < 64) qs[tid] = g_q[bi * 64 + tid];

    // --- A tiles: k[b, j0+j, e] -> fp16 hi/lo ---
    {
        const float* kbase = g_k + ((size_t)b * 512 + j0) * 64;
        #pragma unroll
        for (int it = tid; it < 128 * 32; it += 256) {   // float2 elements
            int row = it >> 5, p = it & 31;
            float2 v = *(const float2*)(kbase + row * 64 + p * 2);
            __half2 hi = __floats2half2_rn(v.x, v.y);
            float2 hf = __half22float2(hi);
            __half2 lo = __floats2half2_rn(v.x - hf.x, v.y - hf.y);
            int off = row * PITCH_B + p * 4;
            *(__half2*)(smem + SM_A_HI + off) = hi;
            *(__half2*)(smem + SM_A_LO + off) = lo;
        }
    }
    __syncthreads();   // qs visible

    // --- B tiles: (q[e] * Wv[d0+r, e]) -> fp16 hi/lo ---
    {
        const float* wvbase = Wv + (size_t)d0 * 64;
        #pragma unroll
        for (int it = tid; it < 128 * 32; it += 256) {
            int row = it >> 5, p = it & 31;
            float2 w = *(const float2*)(wvbase + row * 64 + p * 2);
            float vx = qs[p * 2] * w.x;
            float vy = qs[p * 2 + 1] * w.y;
            __half2 hi = __floats2half2_rn(vx, vy);
            float2 hf = __half22float2(hi);
            __half2 lo = __floats2half2_rn(vx - hf.x, vy - hf.y);
            int off = row * PITCH_B + p * 4;
            *(__half2*)(smem + SM_B_HI + off) = hi;
            *(__half2*)(smem + SM_B_LO + off) = lo;
        }
    }
    __syncthreads();

    // --- warp tiling: warp_m = wid>>2 (2 x 64 rows), warp_n = wid&3 (4 x 32 cols)
    int m0 = (wid >> 2) * 64;
    int n0 = (wid & 3) * 32;

    float acc[4][4][4];     // [mt][nt][reg]
    #pragma unroll
    for (int mt = 0; mt < 4; mt++)
        #pragma unroll
        for (int nt = 0; nt < 4; nt++)
            #pragma unroll
            for (int r = 0; r < 4; r++) acc[mt][nt][r] = 0.f;

    // per-lane fragment base offsets (bytes)
    int aRow = m0 + (lid >> 2);
    int aCol = (lid & 3) * 2;
    int bRow = n0 + (lid >> 2);

    // 3 passes: (Ahi,Bhi), (Ahi,Blo), (Alo,Bhi)
    #pragma unroll
    for (int pass = 0; pass < 3; pass++) {
        const char* As = smem + (pass == 2 ? SM_A_LO : SM_A_HI);
        const char* Bs = smem + (pass == 1 ? SM_B_LO : SM_B_HI);

        #pragma unroll
        for (int ks = 0; ks < 4; ks++) {
            int e0 = ks * 16;
            uint32_t afrag[4][4], bfrag[4][2];
            #pragma unroll
            for (int mt = 0; mt < 4; mt++) {
                const char* pa = As + (aRow + mt * 16) * PITCH_B + (e0 + aCol) * 2;
                afrag[mt][0] = *(const uint32_t*)(pa);
                afrag[mt][1] = *(const uint32_t*)(pa + 8 * PITCH_B);
                afrag[mt][2] = *(const uint32_t*)(pa + 16);
                afrag[mt][3] = *(const uint32_t*)(pa + 8 * PITCH_B + 16);
            }
            #pragma unroll
            for (int nt = 0; nt < 4; nt++) {
                const char* pb = Bs + (bRow + nt * 8) * PITCH_B + (e0 + aCol) * 2;
                bfrag[nt][0] = *(const uint32_t*)(pb);
                bfrag[nt][1] = *(const uint32_t*)(pb + 16);
            }
            #pragma unroll
            for (int mt = 0; mt < 4; mt++)
                #pragma unroll
                for (int nt = 0; nt < 4; nt++)
                    mma16816(acc[mt][nt], afrag[mt], bfrag[nt]);
        }
    }

    // --- epilogue: direct stores (float2 pairs, full 32B sectors) ---
    size_t obase = (size_t)bi * 512 * 512;
    int rowA = j0 + m0 + (lid >> 2);
    int colA = d0 + n0 + (lid & 3) * 2;
    #pragma unroll
    for (int mt = 0; mt < 4; mt++) {
        int r0 = rowA + mt * 16;
        float* orow0 = out + obase + (size_t)r0 * 512;
        float* orow1 = orow0 + 8 * 512;
        #pragma unroll
        for (int nt = 0; nt < 4; nt++) {
            int c = colA + nt * 8;
            *(float2*)(orow0 + c) = make_float2(acc[mt][nt][0], acc[mt][nt][1]);
            *(float2*)(orow1 + c) = make_float2(acc[mt][nt][2], acc[mt][nt][3]);
        }
    }
}

// ---------------------------------------------------------------------------
// launch
// ---------------------------------------------------------------------------
extern "C" void kernel_launch(void* const* d_in, const int* in_sizes, int n_in,
                              void* d_out, int out_size)
{
    const float* t  = (const float*)d_in[0];
    const float* Wq = (const float*)d_in[1];
    const float* Wk = (const float*)d_in[2];
    const float* Wv = (const float*)d_in[3];
    float* out = (float*)d_out;

    cudaFuncSetAttribute(kappa_kernel, cudaFuncAttributeMaxDynamicSharedMemorySize,
                         SMEM_TOTAL);

    qk_kernel<<<1024, 256>>>(t, Wq, Wk);
    kappa_kernel<<<16384, 256, SMEM_TOTAL>>>(Wv, out);
}

// round 3
// speedup vs baseline: 1.1430x; 1.1430x over previous
#include <cuda_runtime.h>
#include <cuda_fp16.h>
#include <cstdint>

// ============================================================================
// QKVHadamard: kappa[b,i,j,d] = sum_e q[b,i,e] * k[b,j,e] * Wv[d,e]
//   q = t @ Wq^T, k = t @ Wk^T   (B=2, N=512, D=512, d_dir=64)
//
// Per (b,i): kappa[j,d] = sum_e (q[e]*k[j,e]) * Wv[d,e]
//   A[j,e] = q[e]*k[j,e]  (split fp16 hi/lo),  B[d,e] = Wv (pre-split hi/lo)
// 3 MMA combos fused in one K loop: Ahi*Bhi + Ahi*Blo + Alo*Bhi, fp32 acc.
// CTA: 128(j) x 128(d), 128 threads, 4 warps 2x2 -> warp tile 64x64.
// ============================================================================

// ---------------------------------------------------------------------------
// global scratch
// ---------------------------------------------------------------------------
__device__ float  g_q[1024 * 64];
__device__ float  g_k[1024 * 64];
__device__ __half g_wv_hi[512 * 64];
__device__ __half g_wv_lo[512 * 64];

// ---------------------------------------------------------------------------
// Kernel 0: split Wv into fp16 hi/lo
// ---------------------------------------------------------------------------
__global__ __launch_bounds__(256) void wv_split_kernel(const float* __restrict__ Wv)
{
    int idx = blockIdx.x * 256 + threadIdx.x;   // 0..32767
    float v = Wv[idx];
    __half hh = __float2half_rn(v);
    __half hl = __float2half_rn(v - __half2float(hh));
    g_wv_hi[idx] = hh;
    g_wv_lo[idx] = hl;
}

// ---------------------------------------------------------------------------
// Kernel 1: q = t@Wq^T, k = t@Wk^T. One block per (b,n) row. fp32 exact.
// ---------------------------------------------------------------------------
__global__ __launch_bounds__(256) void qk_kernel(
    const float* __restrict__ t,
    const float* __restrict__ Wq,
    const float* __restrict__ Wk)
{
    __shared__ float ts[512];
    int bn = blockIdx.x;                   // 0..1023
    const float* trow = t + (size_t)bn * 512;
    int tid = threadIdx.x;
    ts[tid]       = trow[tid];
    ts[tid + 256] = trow[tid + 256];
    __syncthreads();

    int wid = tid >> 5, lid = tid & 31;
    #pragma unroll
    for (int r = 0; r < 8; r++) {
        int e = wid * 8 + r;               // 0..63
        const float* wq = Wq + (size_t)e * 512;
        const float* wk = Wk + (size_t)e * 512;
        float aq = 0.f, ak = 0.f;
        #pragma unroll 4
        for (int kk = lid; kk < 512; kk += 32) {
            float tv = ts[kk];
            aq += tv * wq[kk];
            ak += tv * wk[kk];
        }
        #pragma unroll
        for (int off = 16; off; off >>= 1) {
            aq += __shfl_xor_sync(0xFFFFFFFFu, aq, off);
            ak += __shfl_xor_sync(0xFFFFFFFFu, ak, off);
        }
        if (lid == 0) {
            g_q[bn * 64 + e] = aq;
            g_k[bn * 64 + e] = ak;
        }
    }
}

// ---------------------------------------------------------------------------
// Kernel 2: per CTA: 128(j) x 128(d) tile of kappa for one (b,i).
// ---------------------------------------------------------------------------
// SMEM: 4 half arrays, 128 rows x 64 cols, row pitch 72 halves (144 bytes).
// 144B = 36 banks -> rows shift 4 banks: fragment loads + ldmatrix conflict-free.
static constexpr int PITCH_B   = 144;
static constexpr int ARR_BYTES = 128 * PITCH_B;       // 18432
static constexpr int SM_A_HI = 0;
static constexpr int SM_A_LO = ARR_BYTES;
static constexpr int SM_B_HI = 2 * ARR_BYTES;
static constexpr int SM_B_LO = 3 * ARR_BYTES;
static constexpr int SM_QS   = 4 * ARR_BYTES;         // 64 floats
static constexpr int SMEM_TOTAL = SM_QS + 64 * 4;     // 73984 bytes

__device__ __forceinline__ uint32_t smem_u32(const void* p) {
    uint32_t a;
    asm("{ .reg .u64 t; cvta.to.shared.u64 t, %1; cvt.u32.u64 %0, t; }"
        : "=r"(a) : "l"(p));
    return a;
}

__device__ __forceinline__ void mma16816(float* c, const uint32_t* a, const uint32_t* b) {
    asm volatile(
        "mma.sync.aligned.m16n8k16.row.col.f32.f16.f16.f32 "
        "{%0,%1,%2,%3}, {%4,%5,%6,%7}, {%8,%9}, {%0,%1,%2,%3};"
        : "+f"(c[0]), "+f"(c[1]), "+f"(c[2]), "+f"(c[3])
        : "r"(a[0]), "r"(a[1]), "r"(a[2]), "r"(a[3]), "r"(b[0]), "r"(b[1]));
}

__device__ __forceinline__ void ldsm_x4(uint32_t* r, uint32_t addr) {
    asm volatile(
        "ldmatrix.sync.aligned.m8n8.x4.shared.b16 {%0,%1,%2,%3}, [%4];"
        : "=r"(r[0]), "=r"(r[1]), "=r"(r[2]), "=r"(r[3]) : "r"(addr));
}

__global__ __launch_bounds__(128) void kappa_kernel(float* __restrict__ out)
{
    extern __shared__ char smem[];
    uint32_t sbase = smem_u32(smem);

    int tid = threadIdx.x, wid = tid >> 5, lid = tid & 31;

    int idx = blockIdx.x;
    int bi  = idx >> 4;          // 0..1023  (b*512 + i)
    int jt  = (idx >> 2) & 3;    // j tile
    int dt  = idx & 3;           // d tile
    int b   = bi >> 9;
    int j0  = jt * 128;
    int d0  = dt * 128;

    // q_i into smem (fp32)
    float* qs = (float*)(smem + SM_QS);
    if (tid < 64) qs[tid] = g_q[bi * 64 + tid];

    // --- B tiles: straight copy of pre-split Wv hi/lo (no qs dependency) ---
    {
        #pragma unroll
        for (int it = tid; it < 128 * 8; it += 128) {   // uint4 (16B) chunks
            int row = it >> 3, c = it & 7;
            const uint4* srcH = (const uint4*)(g_wv_hi + (size_t)(d0 + row) * 64) + c;
            const uint4* srcL = (const uint4*)(g_wv_lo + (size_t)(d0 + row) * 64) + c;
            int off = row * PITCH_B + c * 16;
            *(uint4*)(smem + SM_B_HI + off) = *srcH;
            *(uint4*)(smem + SM_B_LO + off) = *srcL;
        }
    }
    __syncthreads();   // qs visible

    // --- A tiles: (q[e] * k[b, j0+j, e]) -> fp16 hi/lo ---
    {
        const float*  kbase = g_k + ((size_t)b * 512 + j0) * 64;
        const float2* k2    = (const float2*)kbase;
        const float2* q2    = (const float2*)qs;
        #pragma unroll
        for (int it = tid; it < 128 * 32; it += 128) {   // float2 elements
            int row = it >> 5, p = it & 31;
            float2 kv = k2[it];
            float2 qv = q2[p];
            float vx = qv.x * kv.x;
            float vy = qv.y * kv.y;
            __half2 hi = __floats2half2_rn(vx, vy);
            float2 hf = __half22float2(hi);
            __half2 lo = __floats2half2_rn(vx - hf.x, vy - hf.y);
            int off = row * PITCH_B + p * 4;
            *(__half2*)(smem + SM_A_HI + off) = hi;
            *(__half2*)(smem + SM_A_LO + off) = lo;
        }
    }
    __syncthreads();

    // --- warp tiling: 2x2 warps, each 64(m) x 64(n) ---
    int m0 = (wid >> 1) * 64;
    int n0 = (wid & 1) * 64;

    float acc[4][8][4];     // [mt][nt][reg] = 128 regs
    #pragma unroll
    for (int mt = 0; mt < 4; mt++)
        #pragma unroll
        for (int nt = 0; nt < 8; nt++)
            #pragma unroll
            for (int r = 0; r < 4; r++) acc[mt][nt][r] = 0.f;

    // per-lane base addresses
    // ldmatrix A: lanes 0-15 -> rows, lanes 16-31 -> rows at col+8
    uint32_t aLdsmHi = sbase + SM_A_HI + (uint32_t)(m0 + (lid & 15)) * PITCH_B
                     + (uint32_t)((lid >> 4) << 4);
    uint32_t aLdsmLo = aLdsmHi + (SM_A_LO - SM_A_HI);
    // B scalar loads: row = n0 + (lid>>2), col byte = (lid&3)*4
    const char* pBHi = smem + SM_B_HI + (n0 + (lid >> 2)) * PITCH_B + (lid & 3) * 4;
    const char* pBLo = smem + SM_B_LO + (n0 + (lid >> 2)) * PITCH_B + (lid & 3) * 4;

    #pragma unroll
    for (int ks = 0; ks < 4; ks++) {
        uint32_t koff = ks * 32;   // 16 halves

        uint32_t bhi[8][2], blo[8][2];
        #pragma unroll
        for (int nt = 0; nt < 8; nt++) {
            const char* ph = pBHi + nt * 8 * PITCH_B + koff;
            const char* pl = pBLo + nt * 8 * PITCH_B + koff;
            bhi[nt][0] = *(const uint32_t*)(ph);
            bhi[nt][1] = *(const uint32_t*)(ph + 16);
            blo[nt][0] = *(const uint32_t*)(pl);
            blo[nt][1] = *(const uint32_t*)(pl + 16);
        }

        uint32_t af[4][4];
        #pragma unroll
        for (int mt = 0; mt < 4; mt++)
            ldsm_x4(af[mt], aLdsmHi + mt * 16 * PITCH_B + koff);

        #pragma unroll
        for (int mt = 0; mt < 4; mt++)
            #pragma unroll
            for (int nt = 0; nt < 8; nt++) {
                mma16816(acc[mt][nt], af[mt], bhi[nt]);
                mma16816(acc[mt][nt], af[mt], blo[nt]);
            }

        #pragma unroll
        for (int mt = 0; mt < 4; mt++)
            ldsm_x4(af[mt], aLdsmLo + mt * 16 * PITCH_B + koff);

        #pragma unroll
        for (int mt = 0; mt < 4; mt++)
            #pragma unroll
            for (int nt = 0; nt < 8; nt++)
                mma16816(acc[mt][nt], af[mt], bhi[nt]);
    }

    // --- epilogue: direct stores (float2 pairs) ---
    size_t obase = (size_t)bi * 512 * 512;
    int rowA = j0 + m0 + (lid >> 2);
    int colA = d0 + n0 + (lid & 3) * 2;
    #pragma unroll
    for (int mt = 0; mt < 4; mt++) {
        int r0 = rowA + mt * 16;
        float* orow0 = out + obase + (size_t)r0 * 512;
        float* orow1 = orow0 + 8 * 512;
        #pragma unroll
        for (int nt = 0; nt < 8; nt++) {
            int c = colA + nt * 8;
            *(float2*)(orow0 + c) = make_float2(acc[mt][nt][0], acc[mt][nt][1]);
            *(float2*)(orow1 + c) = make_float2(acc[mt][nt][2], acc[mt][nt][3]);
        }
    }
}

// ---------------------------------------------------------------------------
// launch
// ---------------------------------------------------------------------------
extern "C" void kernel_launch(void* const* d_in, const int* in_sizes, int n_in,
                              void* d_out, int out_size)
{
    const float* t  = (const float*)d_in[0];
    const float* Wq = (const float*)d_in[1];
    const float* Wk = (const float*)d_in[2];
    const float* Wv = (const float*)d_in[3];
    float* out = (float*)d_out;

    cudaFuncSetAttribute(kappa_kernel, cudaFuncAttributeMaxDynamicSharedMemorySize,
                         SMEM_TOTAL);

    wv_split_kernel<<<128, 256>>>(Wv);
    qk_kernel<<<1024, 256>>>(t, Wq, Wk);
    kappa_kernel<<<16384, 128, SMEM_TOTAL>>>(out);
}

// round 4
// speedup vs baseline: 1.4089x; 1.2327x over previous
#include <cuda_runtime.h>
#include <cuda_fp16.h>
#include <cstdint>

// ============================================================================
// QKVHadamard: kappa[b,i,j,d] = sum_e q[b,i,e] * k[b,j,e] * Wv[d,e]
//   q = t @ Wq^T, k = t @ Wk^T   (B=2, N=512, D=512, d_dir=64)
//
// Per (b,i): kappa[j,d] = sum_e (q[e]*k[j,e]) * Wv[d,e]
//   A[j,e] = q[e]*k[j,e]  (split fp16 hi/lo),  B[d,e] = Wv (pre-split hi/lo)
// 3 MMA combos fused: Ahi*Bhi + Ahi*Blo + Alo*Bhi, fp32 acc -> ~1e-6 rel err.
// CTA: 128(j) x [4 x 128(d) persistent loop], 128 threads, warp tile 64x64.
// B double-buffered via cp.async; all fragments via ldmatrix.x4.
// ============================================================================

// ---------------------------------------------------------------------------
// global scratch
// ---------------------------------------------------------------------------
__device__ float  g_q[1024 * 64];
__device__ float  g_k[1024 * 64];
__device__ __half g_wv_hi[512 * 64];
__device__ __half g_wv_lo[512 * 64];

// ---------------------------------------------------------------------------
// Prologue (fused): blocks 0..1023 -> q,k rows; blocks 1024..1151 -> Wv split
// ---------------------------------------------------------------------------
__global__ __launch_bounds__(256) void prologue_kernel(
    const float* __restrict__ t,
    const float* __restrict__ Wq,
    const float* __restrict__ Wk,
    const float* __restrict__ Wv)
{
    int tid = threadIdx.x;
    if (blockIdx.x >= 1024) {
        int idx = (blockIdx.x - 1024) * 256 + tid;   // 0..32767
        float v = Wv[idx];
        __half hh = __float2half_rn(v);
        __half hl = __float2half_rn(v - __half2float(hh));
        g_wv_hi[idx] = hh;
        g_wv_lo[idx] = hl;
        return;
    }

    __shared__ float ts[512];
    int bn = blockIdx.x;                   // 0..1023
    const float* trow = t + (size_t)bn * 512;
    ts[tid]       = trow[tid];
    ts[tid + 256] = trow[tid + 256];
    __syncthreads();

    int wid = tid >> 5, lid = tid & 31;
    #pragma unroll
    for (int r = 0; r < 8; r++) {
        int e = wid * 8 + r;               // 0..63
        const float* wq = Wq + (size_t)e * 512;
        const float* wk = Wk + (size_t)e * 512;
        float aq = 0.f, ak = 0.f;
        #pragma unroll 4
        for (int kk = lid; kk < 512; kk += 32) {
            float tv = ts[kk];
            aq += tv * wq[kk];
            ak += tv * wk[kk];
        }
        #pragma unroll
        for (int off = 16; off; off >>= 1) {
            aq += __shfl_xor_sync(0xFFFFFFFFu, aq, off);
            ak += __shfl_xor_sync(0xFFFFFFFFu, ak, off);
        }
        if (lid == 0) {
            g_q[bn * 64 + e] = aq;
            g_k[bn * 64 + e] = ak;
        }
    }
}

// ---------------------------------------------------------------------------
// Main kernel
// ---------------------------------------------------------------------------
// SMEM: half arrays 128 rows x 64 cols, row pitch 144 bytes (36 banks ->
// rows shift 4 banks: ldmatrix / cp.async conflict-free, 16B-aligned).
static constexpr int PITCH_B   = 144;
static constexpr int ARR_BYTES = 128 * PITCH_B;       // 18432
static constexpr int SM_A_HI = 0;
static constexpr int SM_A_LO = ARR_BYTES;
static constexpr int SM_B0   = 2 * ARR_BYTES;         // buf0: hi at +0, lo at +ARR
static constexpr int SM_B1   = 4 * ARR_BYTES;         // buf1
static constexpr int SM_QS   = 6 * ARR_BYTES;         // 64 floats
static constexpr int SMEM_TOTAL = SM_QS + 64 * 4;     // 110848 bytes

__device__ __forceinline__ uint32_t smem_u32(const void* p) {
    uint32_t a;
    asm("{ .reg .u64 t; cvta.to.shared.u64 t, %1; cvt.u32.u64 %0, t; }"
        : "=r"(a) : "l"(p));
    return a;
}

__device__ __forceinline__ void mma16816(float* c, const uint32_t* a,
                                         uint32_t b0, uint32_t b1) {
    asm volatile(
        "mma.sync.aligned.m16n8k16.row.col.f32.f16.f16.f32 "
        "{%0,%1,%2,%3}, {%4,%5,%6,%7}, {%8,%9}, {%0,%1,%2,%3};"
        : "+f"(c[0]), "+f"(c[1]), "+f"(c[2]), "+f"(c[3])
        : "r"(a[0]), "r"(a[1]), "r"(a[2]), "r"(a[3]), "r"(b0), "r"(b1));
}

__device__ __forceinline__ void ldsm_x4(uint32_t* r, uint32_t addr) {
    asm volatile(
        "ldmatrix.sync.aligned.m8n8.x4.shared.b16 {%0,%1,%2,%3}, [%4];"
        : "=r"(r[0]), "=r"(r[1]), "=r"(r[2]), "=r"(r[3]) : "r"(addr));
}

__device__ __forceinline__ void cp16(uint32_t dst, const void* src) {
    asm volatile("cp.async.cg.shared.global [%0], [%1], 16;"
                 :: "r"(dst), "l"(src) : "memory");
}
__device__ __forceinline__ void cp_commit() {
    asm volatile("cp.async.commit_group;" ::: "memory");
}
template <int N>
__device__ __forceinline__ void cp_wait() {
    asm volatile("cp.async.wait_group %0;" :: "n"(N) : "memory");
}

// async-copy one d-tile of pre-split Wv (hi+lo) into a B buffer
__device__ __forceinline__ void copy_b_async(uint32_t buf_base, int d0, int tid) {
    #pragma unroll
    for (int s = 0; s < 16; s++) {
        int it  = tid + 128 * s;           // 0..2047
        int arr = it >> 10;                // 0 = hi, 1 = lo
        int rem = it & 1023;
        int row = rem >> 3;
        int c   = rem & 7;
        const __half* src = (arr ? g_wv_lo : g_wv_hi) + (size_t)(d0 + row) * 64 + c * 8;
        uint32_t dst = buf_base + arr * ARR_BYTES + row * PITCH_B + c * 16;
        cp16(dst, src);
    }
}

__global__ __launch_bounds__(128, 2) void kappa_kernel(float* __restrict__ out)
{
    extern __shared__ char smem[];
    uint32_t sbase = smem_u32(smem);

    int tid = threadIdx.x, wid = tid >> 5, lid = tid & 31;

    int idx = blockIdx.x;       // 0..4095
    int bi  = idx >> 2;         // 0..1023 (b*512 + i)
    int jt  = idx & 3;          // j tile
    int b   = bi >> 9;
    int j0  = jt * 128;

    // kick off B copy for dt=0 immediately
    copy_b_async(sbase + SM_B0, 0, tid);
    cp_commit();

    // q_i into smem (fp32)
    float* qs = (float*)(smem + SM_QS);
    if (tid < 64) qs[tid] = g_q[bi * 64 + tid];
    __syncthreads();

    // --- A tiles: (q[e] * k[b, j0+j, e]) -> fp16 hi/lo ---
    {
        const float2* k2 = (const float2*)(g_k + ((size_t)b * 512 + j0) * 64);
        const float2* q2 = (const float2*)qs;
        #pragma unroll
        for (int it = tid; it < 128 * 32; it += 128) {   // float2 elements
            int row = it >> 5, p = it & 31;
            float2 kv = k2[it];
            float2 qv = q2[p];
            float vx = qv.x * kv.x;
            float vy = qv.y * kv.y;
            __half2 hi = __floats2half2_rn(vx, vy);
            float2 hf = __half22float2(hi);
            __half2 lo = __floats2half2_rn(vx - hf.x, vy - hf.y);
            int off = row * PITCH_B + p * 4;
            *(__half2*)(smem + SM_A_HI + off) = hi;
            *(__half2*)(smem + SM_A_LO + off) = lo;
        }
    }

    // --- warp tiling: 2x2 warps, each 64(m) x 64(n) ---
    int m0 = (wid >> 1) * 64;
    int n0 = (wid & 1) * 64;

    // per-lane ldmatrix addresses
    // A (non-trans, m16 tile): lanes 0-15 rows, lanes 16-31 rows at +16B
    uint32_t aHiAddr = sbase + SM_A_HI + (uint32_t)(m0 + (lid & 15)) * PITCH_B
                     + (uint32_t)((lid >> 4) << 4);
    uint32_t aLoAddr = aHiAddr + ARR_BYTES;
    // B (non-trans on [n][k] storage -> exact B fragments):
    // group g covers n-tiles {2g, 2g+1}: lanes 0-7 rows, 8-15 +16B, 16-23 +8rows, 24-31 +8rows+16B
    uint32_t bRowOff = (uint32_t)(n0 + ((lid >> 4) << 3) + (lid & 7)) * PITCH_B
                     + (uint32_t)(((lid >> 3) & 1) << 4);

    size_t obase = (size_t)bi * 512 * 512;
    int rowA = j0 + m0 + (lid >> 2);
    int colBase = n0 + (lid & 3) * 2;

    #pragma unroll 1
    for (int dt = 0; dt < 4; dt++) {
        uint32_t bufCur  = sbase + (dt & 1 ? SM_B1 : SM_B0);
        uint32_t bufNext = sbase + (dt & 1 ? SM_B0 : SM_B1);

        if (dt < 3) {
            copy_b_async(bufNext, (dt + 1) * 128, tid);
            cp_commit();
            cp_wait<1>();     // current buffer's copy complete
        } else {
            cp_wait<0>();
        }
        __syncthreads();      // A built (dt=0) / prev MMA done; cur B visible

        float acc[4][8][4];
        #pragma unroll
        for (int mt = 0; mt < 4; mt++)
            #pragma unroll
            for (int nt = 0; nt < 8; nt++)
                #pragma unroll
                for (int r = 0; r < 4; r++) acc[mt][nt][r] = 0.f;

        uint32_t bHiBase = bufCur + bRowOff;
        uint32_t bLoBase = bHiBase + ARR_BYTES;

        #pragma unroll
        for (int ks = 0; ks < 4; ks++) {
            uint32_t koff = ks * 32;   // 16 halves

            uint32_t bh[4][4], bl[4][4];
            #pragma unroll
            for (int g = 0; g < 4; g++)
                ldsm_x4(bh[g], bHiBase + g * 16 * PITCH_B + koff);
            #pragma unroll
            for (int g = 0; g < 4; g++)
                ldsm_x4(bl[g], bLoBase + g * 16 * PITCH_B + koff);

            uint32_t af[4][4];
            #pragma unroll
            for (int mt = 0; mt < 4; mt++)
                ldsm_x4(af[mt], aHiAddr + mt * 16 * PITCH_B + koff);

            #pragma unroll
            for (int mt = 0; mt < 4; mt++)
                #pragma unroll
                for (int nt = 0; nt < 8; nt++) {
                    mma16816(acc[mt][nt], af[mt], bh[nt >> 1][(nt & 1) * 2],
                                                   bh[nt >> 1][(nt & 1) * 2 + 1]);
                    mma16816(acc[mt][nt], af[mt], bl[nt >> 1][(nt & 1) * 2],
                                                   bl[nt >> 1][(nt & 1) * 2 + 1]);
                }

            #pragma unroll
            for (int mt = 0; mt < 4; mt++)
                ldsm_x4(af[mt], aLoAddr + mt * 16 * PITCH_B + koff);

            #pragma unroll
            for (int mt = 0; mt < 4; mt++)
                #pragma unroll
                for (int nt = 0; nt < 8; nt++)
                    mma16816(acc[mt][nt], af[mt], bh[nt >> 1][(nt & 1) * 2],
                                                   bh[nt >> 1][(nt & 1) * 2 + 1]);
        }

        // --- epilogue for this d tile ---
        int colA = dt * 128 + colBase;
        #pragma unroll
        for (int mt = 0; mt < 4; mt++) {
            float* orow0 = out + obase + (size_t)(rowA + mt * 16) * 512;
            float* orow1 = orow0 + 8 * 512;
            #pragma unroll
            for (int nt = 0; nt < 8; nt++) {
                int c = colA + nt * 8;
                *(float2*)(orow0 + c) = make_float2(acc[mt][nt][0], acc[mt][nt][1]);
                *(float2*)(orow1 + c) = make_float2(acc[mt][nt][2], acc[mt][nt][3]);
            }
        }

        __syncthreads();   // all warps done reading bufCur before it is refilled
    }
}

// ---------------------------------------------------------------------------
// launch
// ---------------------------------------------------------------------------
extern "C" void kernel_launch(void* const* d_in, const int* in_sizes, int n_in,
                              void* d_out, int out_size)
{
    const float* t  = (const float*)d_in[0];
    const float* Wq = (const float*)d_in[1];
    const float* Wk = (const float*)d_in[2];
    const float* Wv = (const float*)d_in[3];
    float* out = (float*)d_out;

    cudaFuncSetAttribute(kappa_kernel, cudaFuncAttributeMaxDynamicSharedMemorySize,
                         SMEM_TOTAL);

    prologue_kernel<<<1152, 256>>>(t, Wq, Wk, Wv);
    kappa_kernel<<<4096, 128, SMEM_TOTAL>>>(out);
}

// round 5
// speedup vs baseline: 1.6032x; 1.1379x over previous
#include <cuda_runtime.h>
#include <cuda_fp16.h>
#include <cstdint>

// ============================================================================
// QKVHadamard: kappa[b,i,j,d] = sum_e q[b,i,e] * k[b,j,e] * Wv[d,e]
//   q = t @ Wq^T, k = t @ Wk^T   (B=2, N=512, D=512, d_dir=64)
//
// Per (b,i): kappa[j,d] = sum_e (q[e]*k[j,e]) * Wv[d,e]
//   A[j,e] = rn_fp16(q[e]*k[j,e])   (single fp16)
//   B[d,e] = Wv split fp16 hi/lo    (pre-split in global)
// 2 MMA passes: A*Bhi + A*Blo = A * (Wv to 22 bits), fp32 acc.
// Dropped term sum_e a_lo*b -> rel err ~2.8e-4 (norm), under 1e-3.
// CTA: 128(j) x [4 x 128(d) persistent loop], 128 threads, warp tile 64x64.
// B double-buffered via cp.async; all fragments via ldmatrix.x4.
// ============================================================================

// ---------------------------------------------------------------------------
// global scratch
// ---------------------------------------------------------------------------
__device__ float  g_q[1024 * 64];
__device__ float  g_k[1024 * 64];
__device__ __half g_wv_hi[512 * 64];
__device__ __half g_wv_lo[512 * 64];

// ---------------------------------------------------------------------------
// Prologue (fused): blocks 0..1023 -> q,k rows; blocks 1024..1151 -> Wv split
// ---------------------------------------------------------------------------
__global__ __launch_bounds__(256) void prologue_kernel(
    const float* __restrict__ t,
    const float* __restrict__ Wq,
    const float* __restrict__ Wk,
    const float* __restrict__ Wv)
{
    int tid = threadIdx.x;
    if (blockIdx.x >= 1024) {
        int idx = (blockIdx.x - 1024) * 256 + tid;   // 0..32767
        float v = Wv[idx];
        __half hh = __float2half_rn(v);
        __half hl = __float2half_rn(v - __half2float(hh));
        g_wv_hi[idx] = hh;
        g_wv_lo[idx] = hl;
        return;
    }

    __shared__ float ts[512];
    int bn = blockIdx.x;                   // 0..1023
    const float* trow = t + (size_t)bn * 512;
    ts[tid]       = trow[tid];
    ts[tid + 256] = trow[tid + 256];
    __syncthreads();

    int wid = tid >> 5, lid = tid & 31;
    #pragma unroll
    for (int r = 0; r < 8; r++) {
        int e = wid * 8 + r;               // 0..63
        const float* wq = Wq + (size_t)e * 512;
        const float* wk = Wk + (size_t)e * 512;
        float aq = 0.f, ak = 0.f;
        #pragma unroll 4
        for (int kk = lid; kk < 512; kk += 32) {
            float tv = ts[kk];
            aq += tv * wq[kk];
            ak += tv * wk[kk];
        }
        #pragma unroll
        for (int off = 16; off; off >>= 1) {
            aq += __shfl_xor_sync(0xFFFFFFFFu, aq, off);
            ak += __shfl_xor_sync(0xFFFFFFFFu, ak, off);
        }
        if (lid == 0) {
            g_q[bn * 64 + e] = aq;
            g_k[bn * 64 + e] = ak;
        }
    }
}

// ---------------------------------------------------------------------------
// Main kernel
// ---------------------------------------------------------------------------
// SMEM: half arrays 128 rows x 64 cols, row pitch 144 bytes (36 banks ->
// rows shift 4 banks: ldmatrix / cp.async conflict-free, 16B-aligned).
static constexpr int PITCH_B   = 144;
static constexpr int ARR_BYTES = 128 * PITCH_B;       // 18432
static constexpr int SM_A   = 0;                      // A (hi only)
static constexpr int SM_B0  = ARR_BYTES;              // buf0: hi at +0, lo at +ARR
static constexpr int SM_B1  = 3 * ARR_BYTES;          // buf1
static constexpr int SM_QS  = 5 * ARR_BYTES;          // 64 floats
static constexpr int SMEM_TOTAL = SM_QS + 64 * 4;     // 92416 bytes

__device__ __forceinline__ uint32_t smem_u32(const void* p) {
    uint32_t a;
    asm("{ .reg .u64 t; cvta.to.shared.u64 t, %1; cvt.u32.u64 %0, t; }"
        : "=r"(a) : "l"(p));
    return a;
}

__device__ __forceinline__ void mma16816(float* c, const uint32_t* a,
                                         uint32_t b0, uint32_t b1) {
    asm volatile(
        "mma.sync.aligned.m16n8k16.row.col.f32.f16.f16.f32 "
        "{%0,%1,%2,%3}, {%4,%5,%6,%7}, {%8,%9}, {%0,%1,%2,%3};"
        : "+f"(c[0]), "+f"(c[1]), "+f"(c[2]), "+f"(c[3])
        : "r"(a[0]), "r"(a[1]), "r"(a[2]), "r"(a[3]), "r"(b0), "r"(b1));
}

__device__ __forceinline__ void ldsm_x4(uint32_t* r, uint32_t addr) {
    asm volatile(
        "ldmatrix.sync.aligned.m8n8.x4.shared.b16 {%0,%1,%2,%3}, [%4];"
        : "=r"(r[0]), "=r"(r[1]), "=r"(r[2]), "=r"(r[3]) : "r"(addr));
}

__device__ __forceinline__ void cp16(uint32_t dst, const void* src) {
    asm volatile("cp.async.cg.shared.global [%0], [%1], 16;"
                 :: "r"(dst), "l"(src) : "memory");
}
__device__ __forceinline__ void cp_commit() {
    asm volatile("cp.async.commit_group;" ::: "memory");
}
template <int N>
__device__ __forceinline__ void cp_wait() {
    asm volatile("cp.async.wait_group %0;" :: "n"(N) : "memory");
}

// async-copy one d-tile of pre-split Wv (hi+lo) into a B buffer
__device__ __forceinline__ void copy_b_async(uint32_t buf_base, int d0, int tid) {
    #pragma unroll
    for (int s = 0; s < 16; s++) {
        int it  = tid + 128 * s;           // 0..2047
        int arr = it >> 10;                // 0 = hi, 1 = lo
        int rem = it & 1023;
        int row = rem >> 3;
        int c   = rem & 7;
        const __half* src = (arr ? g_wv_lo : g_wv_hi) + (size_t)(d0 + row) * 64 + c * 8;
        uint32_t dst = buf_base + arr * ARR_BYTES + row * PITCH_B + c * 16;
        cp16(dst, src);
    }
}

__global__ __launch_bounds__(128, 2) void kappa_kernel(float* __restrict__ out)
{
    extern __shared__ char smem[];
    uint32_t sbase = smem_u32(smem);

    int tid = threadIdx.x, wid = tid >> 5, lid = tid & 31;

    int idx = blockIdx.x;       // 0..4095
    int bi  = idx >> 2;         // 0..1023 (b*512 + i)
    int jt  = idx & 3;          // j tile
    int b   = bi >> 9;
    int j0  = jt * 128;

    // kick off B copy for dt=0 immediately
    copy_b_async(sbase + SM_B0, 0, tid);
    cp_commit();

    // q_i into smem (fp32)
    float* qs = (float*)(smem + SM_QS);
    if (tid < 64) qs[tid] = g_q[bi * 64 + tid];
    __syncthreads();

    // --- A tile: rn_fp16(q[e] * k[b, j0+j, e]) ---
    {
        const float2* k2 = (const float2*)(g_k + ((size_t)b * 512 + j0) * 64);
        const float2* q2 = (const float2*)qs;
        #pragma unroll
        for (int it = tid; it < 128 * 32; it += 128) {   // float2 elements
            int row = it >> 5, p = it & 31;
            float2 kv = k2[it];
            float2 qv = q2[p];
            __half2 hi = __floats2half2_rn(qv.x * kv.x, qv.y * kv.y);
            *(__half2*)(smem + SM_A + row * PITCH_B + p * 4) = hi;
        }
    }

    // --- warp tiling: 2x2 warps, each 64(m) x 64(n) ---
    int m0 = (wid >> 1) * 64;
    int n0 = (wid & 1) * 64;

    // per-lane ldmatrix addresses
    // A (non-trans, m16 tile): lanes 0-15 rows, lanes 16-31 rows at +16B
    uint32_t aAddr = sbase + SM_A + (uint32_t)(m0 + (lid & 15)) * PITCH_B
                   + (uint32_t)((lid >> 4) << 4);
    // B (non-trans on [n][k] storage -> exact B fragments):
    // group g covers n-tiles {2g, 2g+1}
    uint32_t bRowOff = (uint32_t)(n0 + ((lid >> 4) << 3) + (lid & 7)) * PITCH_B
                     + (uint32_t)(((lid >> 3) & 1) << 4);

    size_t obase = (size_t)bi * 512 * 512;
    int rowA = j0 + m0 + (lid >> 2);
    int colBase = n0 + (lid & 3) * 2;

    #pragma unroll 1
    for (int dt = 0; dt < 4; dt++) {
        uint32_t bufCur  = sbase + (dt & 1 ? SM_B1 : SM_B0);
        uint32_t bufNext = sbase + (dt & 1 ? SM_B0 : SM_B1);

        if (dt < 3) {
            copy_b_async(bufNext, (dt + 1) * 128, tid);
            cp_commit();
            cp_wait<1>();     // current buffer's copy complete
        } else {
            cp_wait<0>();
        }
        __syncthreads();      // A built (dt=0) / prev MMA done; cur B visible

        float acc[4][8][4];
        #pragma unroll
        for (int mt = 0; mt < 4; mt++)
            #pragma unroll
            for (int nt = 0; nt < 8; nt++)
                #pragma unroll
                for (int r = 0; r < 4; r++) acc[mt][nt][r] = 0.f;

        uint32_t bHiBase = bufCur + bRowOff;
        uint32_t bLoBase = bHiBase + ARR_BYTES;

        #pragma unroll
        for (int ks = 0; ks < 4; ks++) {
            uint32_t koff = ks * 32;   // 16 halves

            uint32_t bh[4][4], bl[4][4];
            #pragma unroll
            for (int g = 0; g < 4; g++)
                ldsm_x4(bh[g], bHiBase + g * 16 * PITCH_B + koff);
            #pragma unroll
            for (int g = 0; g < 4; g++)
                ldsm_x4(bl[g], bLoBase + g * 16 * PITCH_B + koff);

            uint32_t af[4][4];
            #pragma unroll
            for (int mt = 0; mt < 4; mt++)
                ldsm_x4(af[mt], aAddr + mt * 16 * PITCH_B + koff);

            #pragma unroll
            for (int mt = 0; mt < 4; mt++)
                #pragma unroll
                for (int nt = 0; nt < 8; nt++) {
                    mma16816(acc[mt][nt], af[mt], bh[nt >> 1][(nt & 1) * 2],
                                                   bh[nt >> 1][(nt & 1) * 2 + 1]);
                    mma16816(acc[mt][nt], af[mt], bl[nt >> 1][(nt & 1) * 2],
                                                   bl[nt >> 1][(nt & 1) * 2 + 1]);
                }
        }

        // --- epilogue for this d tile ---
        int colA = dt * 128 + colBase;
        #pragma unroll
        for (int mt = 0; mt < 4; mt++) {
            float* orow0 = out + obase + (size_t)(rowA + mt * 16) * 512;
            float* orow1 = orow0 + 8 * 512;
            #pragma unroll
            for (int nt = 0; nt < 8; nt++) {
                int c = colA + nt * 8;
                *(float2*)(orow0 + c) = make_float2(acc[mt][nt][0], acc[mt][nt][1]);
                *(float2*)(orow1 + c) = make_float2(acc[mt][nt][2], acc[mt][nt][3]);
            }
        }

        __syncthreads();   // all warps done reading bufCur before it is refilled
    }
}

// ---------------------------------------------------------------------------
// launch
// ---------------------------------------------------------------------------
extern "C" void kernel_launch(void* const* d_in, const int* in_sizes, int n_in,
                              void* d_out, int out_size)
{
    const float* t  = (const float*)d_in[0];
    const float* Wq = (const float*)d_in[1];
    const float* Wk = (const float*)d_in[2];
    const float* Wv = (const float*)d_in[3];
    float* out = (float*)d_out;

    cudaFuncSetAttribute(kappa_kernel, cudaFuncAttributeMaxDynamicSharedMemorySize,
                         SMEM_TOTAL);

    prologue_kernel<<<1152, 256>>>(t, Wq, Wk, Wv);
    kappa_kernel<<<4096, 128, SMEM_TOTAL>>>(out);
}

// round 6
// speedup vs baseline: 1.7111x; 1.0673x over previous
#include <cuda_runtime.h>
#include <cuda_fp16.h>
#include <cstdint>

// ============================================================================
// QKVHadamard: kappa[b,i,j,d] = sum_e q[b,i,e] * k[b,j,e] * Wv[d,e]
//   q = t @ Wq^T, k = t @ Wk^T   (B=2, N=512, D=512, d_dir=64)
//
// Per (b,i): kappa[j,d] = sum_e (q[e]*k[j,e]) * Wv[d,e]
//   A[j,e] = rn_fp16(q[e]*k[j,e]); B[d,e] = Wv split fp16 hi/lo (global).
// 2 MMA passes: A*Bhi + A*Blo, fp32 acc -> rel err ~2e-4.
//
// R6: nt-outer loop. A fragments register-resident (loaded once per CTA).
// Per nt: 4 ldsm(B) + 32 HMMA + 8 STG -> stores spread through MMA stream.
// acc live set 16 regs -> ~116 regs total -> 4 CTAs/SM (16 warps).
// Single B buffer (36.9 KB), refilled per d-tile via cp.async.
// ============================================================================

// ---------------------------------------------------------------------------
// global scratch
// ---------------------------------------------------------------------------
__device__ float  g_q[1024 * 64];
__device__ float  g_k[1024 * 64];
__device__ __half g_wv_hi[512 * 64];
__device__ __half g_wv_lo[512 * 64];

// ---------------------------------------------------------------------------
// Prologue (fused): blocks 0..1023 -> q,k rows; blocks 1024..1151 -> Wv split
// ---------------------------------------------------------------------------
__global__ __launch_bounds__(256) void prologue_kernel(
    const float* __restrict__ t,
    const float* __restrict__ Wq,
    const float* __restrict__ Wk,
    const float* __restrict__ Wv)
{
    int tid = threadIdx.x;
    if (blockIdx.x >= 1024) {
        int idx = (blockIdx.x - 1024) * 256 + tid;   // 0..32767
        float v = Wv[idx];
        __half hh = __float2half_rn(v);
        __half hl = __float2half_rn(v - __half2float(hh));
        g_wv_hi[idx] = hh;
        g_wv_lo[idx] = hl;
        return;
    }

    __shared__ float ts[512];
    int bn = blockIdx.x;                   // 0..1023
    const float* trow = t + (size_t)bn * 512;
    ts[tid]       = trow[tid];
    ts[tid + 256] = trow[tid + 256];
    __syncthreads();

    int wid = tid >> 5, lid = tid & 31;
    #pragma unroll
    for (int r = 0; r < 8; r++) {
        int e = wid * 8 + r;               // 0..63
        const float* wq = Wq + (size_t)e * 512;
        const float* wk = Wk + (size_t)e * 512;
        float aq = 0.f, ak = 0.f;
        #pragma unroll 4
        for (int kk = lid; kk < 512; kk += 32) {
            float tv = ts[kk];
            aq += tv * wq[kk];
            ak += tv * wk[kk];
        }
        #pragma unroll
        for (int off = 16; off; off >>= 1) {
            aq += __shfl_xor_sync(0xFFFFFFFFu, aq, off);
            ak += __shfl_xor_sync(0xFFFFFFFFu, ak, off);
        }
        if (lid == 0) {
            g_q[bn * 64 + e] = aq;
            g_k[bn * 64 + e] = ak;
        }
    }
}

// ---------------------------------------------------------------------------
// Main kernel
// ---------------------------------------------------------------------------
// SMEM: half arrays 128 rows x 64 cols, row pitch 144 bytes (36 banks ->
// rows shift 4 banks: ldmatrix / cp.async conflict-free, 16B-aligned).
static constexpr int PITCH_B   = 144;
static constexpr int ARR_BYTES = 128 * PITCH_B;       // 18432
static constexpr int SM_A   = 0;                      // A tile (fp16)
static constexpr int SM_BH  = ARR_BYTES;              // B hi
static constexpr int SM_BL  = 2 * ARR_BYTES;          // B lo
static constexpr int SM_QS  = 3 * ARR_BYTES;          // 64 floats
static constexpr int SMEM_TOTAL = SM_QS + 64 * 4;     // 55552 bytes -> 4 CTAs/SM

__device__ __forceinline__ uint32_t smem_u32(const void* p) {
    uint32_t a;
    asm("{ .reg .u64 t; cvta.to.shared.u64 t, %1; cvt.u32.u64 %0, t; }"
        : "=r"(a) : "l"(p));
    return a;
}

__device__ __forceinline__ void mma16816(float* c, const uint32_t* a,
                                         uint32_t b0, uint32_t b1) {
    asm volatile(
        "mma.sync.aligned.m16n8k16.row.col.f32.f16.f16.f32 "
        "{%0,%1,%2,%3}, {%4,%5,%6,%7}, {%8,%9}, {%0,%1,%2,%3};"
        : "+f"(c[0]), "+f"(c[1]), "+f"(c[2]), "+f"(c[3])
        : "r"(a[0]), "r"(a[1]), "r"(a[2]), "r"(a[3]), "r"(b0), "r"(b1));
}

__device__ __forceinline__ void ldsm_x4(uint32_t* r, uint32_t addr) {
    asm volatile(
        "ldmatrix.sync.aligned.m8n8.x4.shared.b16 {%0,%1,%2,%3}, [%4];"
        : "=r"(r[0]), "=r"(r[1]), "=r"(r[2]), "=r"(r[3]) : "r"(addr));
}

__device__ __forceinline__ void cp16(uint32_t dst, const void* src) {
    asm volatile("cp.async.cg.shared.global [%0], [%1], 16;"
                 :: "r"(dst), "l"(src) : "memory");
}
__device__ __forceinline__ void cp_commit() {
    asm volatile("cp.async.commit_group;" ::: "memory");
}
template <int N>
__device__ __forceinline__ void cp_wait() {
    asm volatile("cp.async.wait_group %0;" :: "n"(N) : "memory");
}

// async-copy one d-tile of pre-split Wv (hi+lo) into the B buffer
__device__ __forceinline__ void copy_b_async(uint32_t sbase, int d0, int tid) {
    #pragma unroll
    for (int s = 0; s < 16; s++) {
        int it  = tid + 128 * s;           // 0..2047
        int arr = it >> 10;                // 0 = hi, 1 = lo
        int rem = it & 1023;
        int row = rem >> 3;
        int c   = rem & 7;
        const __half* src = (arr ? g_wv_lo : g_wv_hi) + (size_t)(d0 + row) * 64 + c * 8;
        uint32_t dst = sbase + (arr ? SM_BL : SM_BH) + row * PITCH_B + c * 16;
        cp16(dst, src);
    }
}

__global__ __launch_bounds__(128, 4) void kappa_kernel(float* __restrict__ out)
{
    extern __shared__ char smem[];
    uint32_t sbase = smem_u32(smem);

    int tid = threadIdx.x, wid = tid >> 5, lid = tid & 31;

    int idx = blockIdx.x;       // 0..4095
    int bi  = idx >> 2;         // 0..1023 (b*512 + i)
    int jt  = idx & 3;          // j tile
    int b   = bi >> 9;
    int j0  = jt * 128;

    // kick off B copy for dt=0 immediately
    copy_b_async(sbase, 0, tid);
    cp_commit();

    // q_i into smem (fp32)
    float* qs = (float*)(smem + SM_QS);
    if (tid < 64) qs[tid] = g_q[bi * 64 + tid];
    __syncthreads();

    // --- A tile: rn_fp16(q[e] * k[b, j0+j, e]) ---
    {
        const float2* k2 = (const float2*)(g_k + ((size_t)b * 512 + j0) * 64);
        const float2* q2 = (const float2*)qs;
        #pragma unroll
        for (int it = tid; it < 128 * 32; it += 128) {   // float2 elements
            int row = it >> 5, p = it & 31;
            float2 kv = k2[it];
            float2 qv = q2[p];
            __half2 hi = __floats2half2_rn(qv.x * kv.x, qv.y * kv.y);
            *(__half2*)(smem + SM_A + row * PITCH_B + p * 4) = hi;
        }
    }
    __syncthreads();

    // --- warp tiling: 2x2 warps, each 64(m) x 64(n) ---
    int m0 = (wid >> 1) * 64;
    int n0 = (wid & 1) * 64;

    // --- load ALL A fragments into registers (A is invariant across dt) ---
    uint32_t afr[4][4][4];   // [mt][ks][reg] = 64 regs
    {
        uint32_t aAddr = sbase + SM_A + (uint32_t)(m0 + (lid & 15)) * PITCH_B
                       + (uint32_t)((lid >> 4) << 4);
        #pragma unroll
        for (int mt = 0; mt < 4; mt++)
            #pragma unroll
            for (int ks = 0; ks < 4; ks++)
                ldsm_x4(afr[mt][ks], aAddr + mt * 16 * PITCH_B + ks * 32);
    }

    // B ldsm addressing: one x4 covers 2 k-steps for an 8-row n-group.
    // lanes 0-7: rows (+chunk 0), 8-15: +16B, 16-23: +32B, 24-31: +48B.
    uint32_t bOff = (uint32_t)(n0 + (lid & 7)) * PITCH_B
                  + (uint32_t)((lid >> 3) << 4);
    uint32_t bhAddr = sbase + SM_BH + bOff;
    uint32_t blAddr = sbase + SM_BL + bOff;

    size_t obase = (size_t)bi * 512 * 512;
    int rowA = j0 + m0 + (lid >> 2);
    float* outw = out + obase + (size_t)rowA * 512;   // row base for mt=0
    int colBase = n0 + (lid & 3) * 2;

    #pragma unroll 1
    for (int dt = 0; dt < 4; dt++) {
        cp_wait<0>();
        __syncthreads();      // B(dt) visible to all warps

        #pragma unroll
        for (int nt = 0; nt < 8; nt++) {
            uint32_t rowStep = nt * 8 * PITCH_B;
            uint32_t bh[8], bl[8];
            ldsm_x4(bh,     bhAddr + rowStep);        // ks0, ks1
            ldsm_x4(bh + 4, bhAddr + rowStep + 64);   // ks2, ks3
            ldsm_x4(bl,     blAddr + rowStep);
            ldsm_x4(bl + 4, blAddr + rowStep + 64);

            float acc[4][4];
            #pragma unroll
            for (int mt = 0; mt < 4; mt++)
                #pragma unroll
                for (int r = 0; r < 4; r++) acc[mt][r] = 0.f;

            #pragma unroll
            for (int ks = 0; ks < 4; ks++)
                #pragma unroll
                for (int mt = 0; mt < 4; mt++) {
                    mma16816(acc[mt], afr[mt][ks], bh[2 * ks], bh[2 * ks + 1]);
                    mma16816(acc[mt], afr[mt][ks], bl[2 * ks], bl[2 * ks + 1]);
                }

            // store this nt column group (8 cols) for all 4 mt
            int c = dt * 128 + colBase + nt * 8;
            #pragma unroll
            for (int mt = 0; mt < 4; mt++) {
                float* orow0 = outw + (size_t)(mt * 16) * 512;
                float* orow1 = orow0 + 8 * 512;
                *(float2*)(orow0 + c) = make_float2(acc[mt][0], acc[mt][1]);
                *(float2*)(orow1 + c) = make_float2(acc[mt][2], acc[mt][3]);
            }
        }

        __syncthreads();      // all warps done reading B before refill
        if (dt < 3) {
            copy_b_async(sbase, (dt + 1) * 128, tid);
            cp_commit();
        }
    }
}

// ---------------------------------------------------------------------------
// launch
// ---------------------------------------------------------------------------
extern "C" void kernel_launch(void* const* d_in, const int* in_sizes, int n_in,
                              void* d_out, int out_size)
{
    const float* t  = (const float*)d_in[0];
    const float* Wq = (const float*)d_in[1];
    const float* Wk = (const float*)d_in[2];
    const float* Wv = (const float*)d_in[3];
    float* out = (float*)d_out;

    cudaFuncSetAttribute(kappa_kernel, cudaFuncAttributeMaxDynamicSharedMemorySize,
                         SMEM_TOTAL);

    prologue_kernel<<<1152, 256>>>(t, Wq, Wk, Wv);
    kappa_kernel<<<4096, 128, SMEM_TOTAL>>>(out);
}

// round 8
// speedup vs baseline: 1.8312x; 1.0701x over previous
#include <cuda_runtime.h>
#include <cuda_fp16.h>
#include <cstdint>

// ============================================================================
// QKVHadamard: kappa[b,i,j,d] = sum_e q[b,i,e] * k[b,j,e] * Wv[d,e]
//   q = t @ Wq^T, k = t @ Wk^T   (B=2, N=512, D=512, d_dir=64)
//
// Per (b,i): kappa[j,d] = sum_e (q[e]*k[j,e]) * Wv[d,e]
//   A[j,e] = rn_fp16(q[e]*k[j,e]);  B[d,e] = rn_fp16(Wv[d,e])
// SINGLE fp16 MMA pass, fp32 acc. Error: two independent fp16-rounding terms
// (~2.1e-4 each, norm) -> ~2.9e-4 total, under the 1e-3 bar with 3.4x margin.
//
// CTA: 128(j) x [4 x 128(d) loop], 128 threads, warp tile 64x64.
// A fragments register-resident (ldsm once, reused for all 4 d-tiles).
// Per nt: 2 ldsm.x4(B) + 16 HMMA + lane-pair shfl + 4 STG.128.
// (R8 = R7 resubmitted after infra-only container failure.)
// ============================================================================

// ---------------------------------------------------------------------------
// global scratch
// ---------------------------------------------------------------------------
__device__ float  g_q[1024 * 64];
__device__ float  g_k[1024 * 64];
__device__ __half g_wv_h[512 * 64];

// ---------------------------------------------------------------------------
// Prologue (fused): blocks 0..1023 -> q,k rows; blocks 1024..1151 -> Wv fp16
// ---------------------------------------------------------------------------
__global__ __launch_bounds__(256) void prologue_kernel(
    const float* __restrict__ t,
    const float* __restrict__ Wq,
    const float* __restrict__ Wk,
    const float* __restrict__ Wv)
{
    int tid = threadIdx.x;
    if (blockIdx.x >= 1024) {
        int idx = (blockIdx.x - 1024) * 256 + tid;   // 0..32767
        g_wv_h[idx] = __float2half_rn(Wv[idx]);
        return;
    }

    __shared__ float ts[512];
    int bn = blockIdx.x;                   // 0..1023
    const float* trow = t + (size_t)bn * 512;
    ts[tid]       = trow[tid];
    ts[tid + 256] = trow[tid + 256];
    __syncthreads();

    int wid = tid >> 5, lid = tid & 31;
    #pragma unroll
    for (int r = 0; r < 8; r++) {
        int e = wid * 8 + r;               // 0..63
        const float* wq = Wq + (size_t)e * 512;
        const float* wk = Wk + (size_t)e * 512;
        float aq = 0.f, ak = 0.f;
        #pragma unroll 4
        for (int kk = lid; kk < 512; kk += 32) {
            float tv = ts[kk];
            aq += tv * wq[kk];
            ak += tv * wk[kk];
        }
        #pragma unroll
        for (int off = 16; off; off >>= 1) {
            aq += __shfl_xor_sync(0xFFFFFFFFu, aq, off);
            ak += __shfl_xor_sync(0xFFFFFFFFu, ak, off);
        }
        if (lid == 0) {
            g_q[bn * 64 + e] = aq;
            g_k[bn * 64 + e] = ak;
        }
    }
}

// ---------------------------------------------------------------------------
// Main kernel
// ---------------------------------------------------------------------------
// SMEM: half arrays 128 rows x 64 cols, row pitch 144 bytes (36 banks ->
// rows shift 4 banks: ldmatrix / cp.async conflict-free, 16B-aligned).
static constexpr int PITCH_B   = 144;
static constexpr int ARR_BYTES = 128 * PITCH_B;       // 18432
static constexpr int SM_A   = 0;                      // A tile (fp16)
static constexpr int SM_BH  = ARR_BYTES;              // B (fp16)
static constexpr int SM_QS  = 2 * ARR_BYTES;          // 64 floats
static constexpr int SMEM_TOTAL = SM_QS + 64 * 4;     // 37120 bytes

__device__ __forceinline__ uint32_t smem_u32(const void* p) {
    uint32_t a;
    asm("{ .reg .u64 t; cvta.to.shared.u64 t, %1; cvt.u32.u64 %0, t; }"
        : "=r"(a) : "l"(p));
    return a;
}

__device__ __forceinline__ void mma16816(float* c, const uint32_t* a,
                                         uint32_t b0, uint32_t b1) {
    asm volatile(
        "mma.sync.aligned.m16n8k16.row.col.f32.f16.f16.f32 "
        "{%0,%1,%2,%3}, {%4,%5,%6,%7}, {%8,%9}, {%0,%1,%2,%3};"
        : "+f"(c[0]), "+f"(c[1]), "+f"(c[2]), "+f"(c[3])
        : "r"(a[0]), "r"(a[1]), "r"(a[2]), "r"(a[3]), "r"(b0), "r"(b1));
}

__device__ __forceinline__ void ldsm_x4(uint32_t* r, uint32_t addr) {
    asm volatile(
        "ldmatrix.sync.aligned.m8n8.x4.shared.b16 {%0,%1,%2,%3}, [%4];"
        : "=r"(r[0]), "=r"(r[1]), "=r"(r[2]), "=r"(r[3]) : "r"(addr));
}

__device__ __forceinline__ void cp16(uint32_t dst, const void* src) {
    asm volatile("cp.async.cg.shared.global [%0], [%1], 16;"
                 :: "r"(dst), "l"(src) : "memory");
}
__device__ __forceinline__ void cp_commit() {
    asm volatile("cp.async.commit_group;" ::: "memory");
}
template <int N>
__device__ __forceinline__ void cp_wait() {
    asm volatile("cp.async.wait_group %0;" :: "n"(N) : "memory");
}

// async-copy one d-tile of fp16 Wv into the B buffer
__device__ __forceinline__ void copy_b_async(uint32_t sbase, int d0, int tid) {
    #pragma unroll
    for (int s = 0; s < 8; s++) {
        int it  = tid + 128 * s;           // 0..1023
        int row = it >> 3;
        int c   = it & 7;
        const __half* src = g_wv_h + (size_t)(d0 + row) * 64 + c * 8;
        uint32_t dst = sbase + SM_BH + row * PITCH_B + c * 16;
        cp16(dst, src);
    }
}

__global__ __launch_bounds__(128, 4) void kappa_kernel(float* __restrict__ out)
{
    extern __shared__ char smem[];
    uint32_t sbase = smem_u32(smem);

    int tid = threadIdx.x, wid = tid >> 5, lid = tid & 31;

    int idx = blockIdx.x;       // 0..4095
    int bi  = idx >> 2;         // 0..1023 (b*512 + i)
    int jt  = idx & 3;          // j tile
    int b   = bi >> 9;
    int j0  = jt * 128;

    // kick off B copy for dt=0 immediately
    copy_b_async(sbase, 0, tid);
    cp_commit();

    // q_i into smem (fp32)
    float* qs = (float*)(smem + SM_QS);
    if (tid < 64) qs[tid] = g_q[bi * 64 + tid];
    __syncthreads();

    // --- A tile: rn_fp16(q[e] * k[b, j0+j, e]) ---
    {
        const float2* k2 = (const float2*)(g_k + ((size_t)b * 512 + j0) * 64);
        const float2* q2 = (const float2*)qs;
        #pragma unroll
        for (int it = tid; it < 128 * 32; it += 128) {   // float2 elements
            int row = it >> 5, p = it & 31;
            float2 kv = k2[it];
            float2 qv = q2[p];
            __half2 hi = __floats2half2_rn(qv.x * kv.x, qv.y * kv.y);
            *(__half2*)(smem + SM_A + row * PITCH_B + p * 4) = hi;
        }
    }
    __syncthreads();

    // --- warp tiling: 2x2 warps, each 64(m) x 64(n) ---
    int m0 = (wid >> 1) * 64;
    int n0 = (wid & 1) * 64;

    // --- load ALL A fragments into registers (A invariant across dt) ---
    uint32_t afr[4][4][4];   // [mt][ks][reg] = 64 regs
    {
        uint32_t aAddr = sbase + SM_A + (uint32_t)(m0 + (lid & 15)) * PITCH_B
                       + (uint32_t)((lid >> 4) << 4);
        #pragma unroll
        for (int mt = 0; mt < 4; mt++)
            #pragma unroll
            for (int ks = 0; ks < 4; ks++)
                ldsm_x4(afr[mt][ks], aAddr + mt * 16 * PITCH_B + ks * 32);
    }

    // B ldsm addressing: one x4 covers 2 k-steps for an 8-row n-group.
    uint32_t bOff = (uint32_t)(n0 + (lid & 7)) * PITCH_B
                  + (uint32_t)((lid >> 3) << 4);
    uint32_t bhAddr = sbase + SM_BH + bOff;

    size_t obase = (size_t)bi * 512 * 512;
    int rowA = j0 + m0 + (lid >> 2);
    int isOdd = lid & 1;
    // even lane stores its own row; odd lane stores row+8
    float* outw = out + obase + (size_t)(rowA + (isOdd ? 8 : 0)) * 512;
    // float4 base col within the warp's 64-col strip
    int colBase = n0 + (((lid & 3) >> 1) << 2);

    #pragma unroll 1
    for (int dt = 0; dt < 4; dt++) {
        cp_wait<0>();
        __syncthreads();      // B(dt) visible to all warps

        #pragma unroll
        for (int nt = 0; nt < 8; nt++) {
            uint32_t rowStep = nt * 8 * PITCH_B;
            uint32_t bh[8];
            ldsm_x4(bh,     bhAddr + rowStep);        // ks0, ks1
            ldsm_x4(bh + 4, bhAddr + rowStep + 64);   // ks2, ks3

            float acc[4][4];
            #pragma unroll
            for (int mt = 0; mt < 4; mt++)
                #pragma unroll
                for (int r = 0; r < 4; r++) acc[mt][r] = 0.f;

            #pragma unroll
            for (int ks = 0; ks < 4; ks++)
                #pragma unroll
                for (int mt = 0; mt < 4; mt++)
                    mma16816(acc[mt], afr[mt][ks], bh[2 * ks], bh[2 * ks + 1]);

            // lane-pair exchange -> one STG.128 per mt
            int c = dt * 128 + colBase + nt * 8;
            #pragma unroll
            for (int mt = 0; mt < 4; mt++) {
                float sx = isOdd ? acc[mt][0] : acc[mt][2];
                float sy = isOdd ? acc[mt][1] : acc[mt][3];
                float rx = __shfl_xor_sync(0xFFFFFFFFu, sx, 1);
                float ry = __shfl_xor_sync(0xFFFFFFFFu, sy, 1);
                float4 v = isOdd
                    ? make_float4(rx, ry, acc[mt][2], acc[mt][3])
                    : make_float4(acc[mt][0], acc[mt][1], rx, ry);
                *(float4*)(outw + (size_t)(mt * 16) * 512 + c) = v;
            }
        }

        __syncthreads();      // all warps done reading B before refill
        if (dt < 3) {
            copy_b_async(sbase, (dt + 1) * 128, tid);
            cp_commit();
        }
    }
}

// ---------------------------------------------------------------------------
// launch
// ---------------------------------------------------------------------------
extern "C" void kernel_launch(void* const* d_in, const int* in_sizes, int n_in,
                              void* d_out, int out_size)
{
    const float* t  = (const float*)d_in[0];
    const float* Wq = (const float*)d_in[1];
    const float* Wk = (const float*)d_in[2];
    const float* Wv = (const float*)d_in[3];
    float* out = (float*)d_out;

    cudaFuncSetAttribute(kappa_kernel, cudaFuncAttributeMaxDynamicSharedMemorySize,
                         SMEM_TOTAL);

    prologue_kernel<<<1152, 256>>>(t, Wq, Wk, Wv);
    kappa_kernel<<<4096, 128, SMEM_TOTAL>>>(out);
}